// round 7
// baseline (speedup 1.0000x reference)
#include <cuda_runtime.h>
#include <stdint.h>
#include <stddef.h>

// SparkFieldNet single step, bit-matching JAX threefry-2x32 RNG
// (jax_threefry_partitionable=True scheme, the modern default).
// Inputs (metadata order): 0=W[N*N] f32, 1=s[N] f32, 2=M[N] f32,
//   3=spark_pos[K] i32, 4=spark_energy[K] f32, 5=spark_age[K] i32
// Output: concat(pos[K], W[N*N], s[N], M[N], energy[K], age[K]) as float32.

#define N 8192
#define K 256

extern "C" __device__ float __nv_logf(float);

// ---- device scratch (static __device__ globals: allowed) ----
__device__ float g_z0[(size_t)K * N];   // gumbel + (div + 0.8*Mdec)  (8MB)
__device__ float g_gum[(size_t)K * N];  // gumbel                      (8MB)
__device__ float g_div[(size_t)K * N];  // (relu(W0[row])+1e-6)/0.3    (8MB)
__device__ float g_Ws[N];
__device__ float g_sState[N];
__device__ float g_Mdec[N];
__device__ int   g_forced[N];
__device__ unsigned g_kc0[K], g_kc1[K];
__device__ int   g_explore[K];
__device__ int   g_randpos[K];

// ---------------- Threefry-2x32 (JAX-exact, 20 rounds) ----------------
__device__ __forceinline__ void tf2x32(unsigned k0, unsigned k1,
                                       unsigned x0, unsigned x1,
                                       unsigned& o0, unsigned& o1) {
  unsigned ks2 = k0 ^ k1 ^ 0x1BD11BDAu;
  x0 += k0; x1 += k1;
#define TFR(r) { x0 += x1; x1 = (x1 << (r)) | (x1 >> (32 - (r))); x1 ^= x0; }
  TFR(13) TFR(15) TFR(26) TFR(6)   x0 += k1;  x1 += ks2 + 1u;
  TFR(17) TFR(29) TFR(16) TFR(24)  x0 += ks2; x1 += k0 + 2u;
  TFR(13) TFR(15) TFR(26) TFR(6)   x0 += k0;  x1 += k1 + 3u;
  TFR(17) TFR(29) TFR(16) TFR(24)  x0 += k1;  x1 += ks2 + 4u;
  TFR(13) TFR(15) TFR(26) TFR(6)   x0 += ks2; x1 += k0 + 5u;
#undef TFR
  o0 = x0; o1 = x1;
}

// Partitionable split/fold_in: key_i = full threefry pair at counter (0, i)
__device__ __forceinline__ void keypair(unsigned k0, unsigned k1, unsigned i,
                                        unsigned& o0, unsigned& o1) {
  tf2x32(k0, k1, 0u, i, o0, o1);
}

// Partitionable random_bits (32-bit): element j = o0 ^ o1 at counter (0, j)
__device__ __forceinline__ unsigned bits32(unsigned k0, unsigned k1, unsigned j) {
  unsigned o0, o1;
  tf2x32(k0, k1, 0u, j, o0, o1);
  return o0 ^ o1;
}

__device__ __forceinline__ float f01(unsigned b) {
  return __fadd_rn(__uint_as_float((b >> 9) | 0x3f800000u), -1.0f);
}

// XLA ErfInv f32 polynomial (Giles)
__device__ __forceinline__ float erfinv_xla(float x) {
  float w = -log1pf(-__fmul_rn(x, x));
  float p;
  if (w < 5.0f) {
    w = w - 2.5f;
    p = 2.81022636e-08f;
    p = fmaf(p, w, 3.43273939e-07f);
    p = fmaf(p, w, -3.5233877e-06f);
    p = fmaf(p, w, -4.39150654e-06f);
    p = fmaf(p, w, 0.00021858087f);
    p = fmaf(p, w, -0.00125372503f);
    p = fmaf(p, w, -0.00417768164f);
    p = fmaf(p, w, 0.246640727f);
    p = fmaf(p, w, 1.50140941f);
  } else {
    w = sqrtf(w) - 3.0f;
    p = -0.000200214257f;
    p = fmaf(p, w, 0.000100950558f);
    p = fmaf(p, w, 0.00134934322f);
    p = fmaf(p, w, -0.00367342844f);
    p = fmaf(p, w, 0.00573950773f);
    p = fmaf(p, w, -0.0076224613f);
    p = fmaf(p, w, 0.00943887047f);
    p = fmaf(p, w, 1.00167406f);
    p = fmaf(p, w, 2.83297682f);
  }
  return p * x;
}

// ---------------- kInit: per-spark keys, explore, randpos, forced ----------------
__global__ void __launch_bounds__(256) kInit(const int* __restrict__ spark_pos,
                                             const int* __restrict__ spark_age) {
  int t = threadIdx.x;
  for (int j = t; j < N; j += 256) g_forced[j] = 0;
  __syncthreads();

  const unsigned B0 = 0u, B1 = 42u;  // jax.random.key(42)
  // split(key, 4) (foldlike): knoise@0, kexp@1, krand@2, kcat@3
  unsigned kexp0, kexp1, krand0, krand1, kcat0, kcat1;
  keypair(B0, B1, 1u, kexp0, kexp1);
  keypair(B0, B1, 2u, krand0, krand1);
  keypair(B0, B1, 3u, kcat0, kcat1);

  int i = t;  // one spark per thread (K == 256)
  // ke_i = split(kexp,256)[i]; explore = uniform(ke_i) < 0.05
  unsigned ke0, ke1;
  keypair(kexp0, kexp1, (unsigned)i, ke0, ke1);
  g_explore[i] = (f01(bits32(ke0, ke1, 0u)) < 0.05f) ? 1 : 0;
  // kr_i = split(krand,256)[i]; randint: k1,k2 = split(kr_i);
  // span=8192 (pow2) and 2^16 % 8192 == 0 => result = lower_bits(k2) & 8191
  unsigned kr0, kr1, k20, k21;
  keypair(krand0, krand1, (unsigned)i, kr0, kr1);
  keypair(kr0, kr1, 1u, k20, k21);
  g_randpos[i] = (int)(bits32(k20, k21, 0u) & (unsigned)(N - 1));
  // kc_i = split(kcat,256)[i]
  unsigned kc0, kc1;
  keypair(kcat0, kcat1, (unsigned)i, kc0, kc1);
  g_kc0[i] = kc0;
  g_kc1[i] = kc1;
  // forced mask (scatter-max of (age < 5))
  if (spark_age[i] < 5) g_forced[spark_pos[i]] = 1;
}

// ---------------- kMV: y = W @ (0.95 s); out_W = clip(0.999 W) ----------------
__global__ void __launch_bounds__(256) kMV(const float* __restrict__ W,
                                           const float* __restrict__ s_in,
                                           float* __restrict__ outW) {
  int r = blockIdx.x;
  const float4* w4 = (const float4*)(W + (size_t)r * N);
  const float4* s4 = (const float4*)s_in;
  float4* o4 = (float4*)(outW + (size_t)r * N);
  float acc = 0.f;
  for (int k = threadIdx.x; k < N / 4; k += 256) {
    float4 w = w4[k];
    float4 sv = s4[k];
    acc += w.x * (sv.x * 0.95f) + w.y * (sv.y * 0.95f)
         + w.z * (sv.z * 0.95f) + w.w * (sv.w * 0.95f);
    float4 o;
    o.x = fminf(fmaxf(__fmul_rn(w.x, 0.999f), -2.f), 2.f);
    o.y = fminf(fmaxf(__fmul_rn(w.y, 0.999f), -2.f), 2.f);
    o.z = fminf(fmaxf(__fmul_rn(w.z, 0.999f), -2.f), 2.f);
    o.w = fminf(fmaxf(__fmul_rn(w.w, 0.999f), -2.f), 2.f);
    o4[k] = o;
  }
  for (int off = 16; off; off >>= 1) acc += __shfl_down_sync(0xffffffffu, acc, off);
  __shared__ float sred[8];
  if ((threadIdx.x & 31) == 0) sred[threadIdx.x >> 5] = acc;
  __syncthreads();
  if (threadIdx.x == 0) {
    float a = 0.f;
    for (int w = 0; w < 8; w++) a += sred[w];
    g_Ws[r] = a;
  }
}

// ---------------- kState: noise -> sigmoid -> forced; M decay ----------------
__device__ __forceinline__ void state_one(int j, unsigned b) {
  const float LO = __int_as_float(0xBF7FFFFF);     // nextafter(-1,0) f32
  const float SQ2 = __int_as_float(0x3FB504F3);    // float32 sqrt(2)
  float f = f01(b);
  // uniform(lo=-0.99999994, hi=1): hi-lo rounds to exactly 2.0f
  float u = fmaxf(LO, __fadd_rn(__fmul_rn(f, 2.0f), LO));
  float nrm = __fmul_rn(SQ2, erfinv_xla(u));
  float noise = __fmul_rn(0.05f, nrm);
  float x = __fadd_rn(g_Ws[j], noise);
  float s = g_forced[j] ? 1.0f : (1.0f / (1.0f + expf(-x)));
  g_sState[j] = s;
}

__global__ void __launch_bounds__(512) kState(const float* __restrict__ M_in) {
  int t = blockIdx.x * 512 + threadIdx.x;  // [0,4096)
  const unsigned B0 = 0u, B1 = 42u;
  unsigned n0, n1;
  keypair(B0, B1, 0u, n0, n1);  // knoise = split(key,4)[0]
  state_one(t,        bits32(n0, n1, (unsigned)t));
  state_one(t + 4096, bits32(n0, n1, (unsigned)(t + 4096)));
  g_Mdec[t]        = __fmul_rn(M_in[t], 0.95f);
  g_Mdec[t + 4096] = __fmul_rn(M_in[t + 4096], 0.95f);
}

// ---------------- kGum: gumbels + static logit parts per spark ----------------
__global__ void __launch_bounds__(1024) kGum(const float* __restrict__ W,
                                             const int* __restrict__ spark_pos) {
  int i = blockIdx.x;
  int row = spark_pos[i];
  unsigned kc0 = g_kc0[i], kc1 = g_kc1[i];
  const float* wrow = W + (size_t)row * N;
  size_t base = (size_t)i * N;
  for (int j = threadIdx.x; j < N; j += 1024) {
    unsigned b = bits32(kc0, kc1, (unsigned)j);
    float u = fmaxf(f01(b), 1.17549435e-38f);      // uniform(tiny, 1)
    float g = -__nv_logf(-__nv_logf(u));
    float dv = __fdiv_rn(__fadd_rn(fmaxf(wrow[j], 0.0f), 1e-6f), 0.3f);
    float z0 = __fadd_rn(g, __fadd_rn(dv, __fmul_rn(0.8f, g_Mdec[j])));
    g_gum[base + j] = g;
    g_div[base + j] = dv;
    g_z0[base + j] = z0;
  }
}

// ---------------- kScan: the 256 serial spark iterations ----------------
// shared: s[N], M[N], pnew[N], c[N] (bits 0..15: patch_row+1, bit16: deposited)
#define SMEM_SCAN (4 * N * 4 + 32 * 8 + 3 * K * 4)

__global__ void __launch_bounds__(1024) kScan(const float* __restrict__ W,
                                              const int* __restrict__ sp,
                                              const float* __restrict__ se,
                                              const int* __restrict__ sa,
                                              float* __restrict__ out) {
  extern __shared__ __align__(16) unsigned char smraw[];
  float* s_sh = (float*)smraw;
  float* M_sh = s_sh + N;
  float* pnew = M_sh + N;
  int*   c_sh = (int*)(pnew + N);
  unsigned long long* red = (unsigned long long*)(c_sh + N);
  int*   res_pos = (int*)(red + 32);
  float* res_e = (float*)(res_pos + K);
  int*   res_age = (int*)(res_e + K);

  int tid = threadIdx.x;
  for (int j = tid; j < N; j += 1024) {
    s_sh[j] = g_sState[j];
    M_sh[j] = g_Mdec[j];
    c_sh[j] = 0;
    pnew[j] = 0.f;
  }
  __syncthreads();

  for (int i = 0; i < K; i++) {
    int r = sp[i];
    size_t base = (size_t)i * N;
    const float* z0p = g_z0 + base;

    unsigned long long best = 0ull;
    for (int j = tid; j < N; j += 1024) {
      int c = c_sh[j];
      float z;
      bool patched = ((c & 0xffff) == (r + 1));
      if ((c >> 16) != 0 || patched) {
        float dv = patched
          ? __fdiv_rn(__fadd_rn(fmaxf(pnew[j], 0.0f), 1e-6f), 0.3f)
          : g_div[base + j];
        z = __fadd_rn(g_gum[base + j], __fadd_rn(dv, __fmul_rn(0.8f, M_sh[j])));
      } else {
        z = z0p[j];
      }
      unsigned zu = __float_as_uint(z);
      zu = (zu & 0x80000000u) ? ~zu : (zu | 0x80000000u);
      unsigned long long pk = ((unsigned long long)zu << 32)
                            | (unsigned)(N - 1 - j);   // tie -> smallest index
      if (pk > best) best = pk;
    }
    for (int o = 16; o; o >>= 1) {
      unsigned long long v = __shfl_down_sync(0xffffffffu, best, o);
      if (v > best) best = v;
    }
    if ((tid & 31) == 0) red[tid >> 5] = best;
    __syncthreads();

    if (tid == 0) {
      unsigned long long b = red[0];
      for (int w = 1; w < 32; w++) if (red[w] > b) b = red[w];
      int cat = (N - 1) - (int)(unsigned)(b & 0xffffffffu);
      int nxt = g_explore[i] ? g_randpos[i] : cat;
      int prev = r;
      // edge update W[nxt, prev] = 0.95*W + 0.05*s[prev]
      int cp = c_sh[prev];
      float wold = ((cp & 0xffff) == (nxt + 1)) ? pnew[prev]
                                                : W[(size_t)nxt * N + prev];
      float wn = __fadd_rn(__fmul_rn(wold, 0.95f), __fmul_rn(s_sh[prev], 0.05f));
      pnew[prev] = wn;
      c_sh[prev] = (cp & ~0xffff) | (nxt + 1);
      // pheromone deposit
      M_sh[nxt] = __fadd_rn(M_sh[nxt], 0.2f);
      c_sh[nxt] |= (1 << 16);
      // energy / state / age
      float e = __fmul_rn(se[i], 0.98f);
      s_sh[nxt] = e;
      int age = sa[i] + 1;
      int pos = nxt;
      if (e < 0.05f) { pos = i % N; e = 1.0f; age = 0; }
      res_pos[i] = pos;
      res_e[i] = e;
      res_age[i] = age;
    }
    __syncthreads();
  }

  // epilogue: outputs (layout: pos[K], W[N*N], s[N], M[N], energy[K], age[K])
  const size_t OUT_W = K;
  const size_t OUT_S = OUT_W + (size_t)N * N;
  const size_t OUT_M = OUT_S + N;
  const size_t OUT_E = OUT_M + N;
  const size_t OUT_A = OUT_E + K;
  for (int j = tid; j < N; j += 1024) {
    out[OUT_S + j] = s_sh[j];
    out[OUT_M + j] = M_sh[j];
    int c = c_sh[j];
    int prow = c & 0xffff;
    if (prow) {  // patch edited W entry (post-decay, post-clip)
      size_t idx = (size_t)(prow - 1) * N + (size_t)j;
      out[OUT_W + idx] = fminf(fmaxf(__fmul_rn(pnew[j], 0.999f), -2.f), 2.f);
    }
  }
  for (int i2 = tid; i2 < K; i2 += 1024) {
    out[i2] = (float)res_pos[i2];
    out[OUT_E + i2] = res_e[i2];
    out[OUT_A + i2] = (float)res_age[i2];
  }
}

// ---------------- launch ----------------
extern "C" void kernel_launch(void* const* d_in, const int* in_sizes, int n_in,
                              void* d_out, int out_size) {
  const float* W = (const float*)d_in[0];
  const float* s = (const float*)d_in[1];
  const float* M = (const float*)d_in[2];
  const int* sp = (const int*)d_in[3];
  const float* se = (const float*)d_in[4];
  const int* sa = (const int*)d_in[5];
  float* out = (float*)d_out;

  cudaFuncSetAttribute(kScan, cudaFuncAttributeMaxDynamicSharedMemorySize,
                       SMEM_SCAN);

  kInit<<<1, 256>>>(sp, sa);
  kMV<<<N, 256>>>(W, s, out + K);      // out_W starts right after pos[K]
  kState<<<8, 512>>>(M);
  kGum<<<K, 1024>>>(W, sp);
  kScan<<<1, 1024, SMEM_SCAN>>>(W, sp, se, sa, out);
}